// round 3
// baseline (speedup 1.0000x reference)
#include <cuda_runtime.h>

// B3-spline à-trous UWT, LEVEL=3.  x:(8,1024,1024) f32 -> (8,4,1024,1024) f32
// Per level j (d=2^j): c_{j+1} = (h x h)*c_j (reflect pad), w_{j+1} = c_j - c_{j+1}.
// Vertical pass uses dilation-matched row chains (4 outputs share 8 tap rows).

#define IMG_H 1024
#define IMG_W 1024
#define NBATCH 8
#define PLANE (IMG_H * IMG_W)
#define W4 (IMG_W / 4)

__device__ float g_scratch1[NBATCH * PLANE];
__device__ float g_scratch2[NBATCH * PLANE];

template <int D>
__global__ __launch_bounds__(256) void uwt_level_kernel(
    const float* __restrict__ cin,
    float* __restrict__ wout, long wbs,
    float* __restrict__ cout, long cbs)
{
    constexpr int HALO = 2 * D;                 // 2, 4, 8
    constexpr int TX = 64, TY = 32;
    constexpr int PADX = ((HALO + 3) / 4) * 4;  // 4, 4, 8
    constexpr int PAD4 = PADX / 4;              // 1, 1, 2
    constexpr int LW  = (D == 4) ? 80 : 76;     // padded pitch (bank-conflict-free chains)
    constexpr int LW4 = LW / 4;                 // 19, 19, 20
    constexpr int SH  = TY + 2 * HALO;          // 36, 40, 48

    __shared__ __align__(16) float s0[SH][LW];  // raw tile (+halo)
    __shared__ __align__(16) float s1[TY][LW];  // after vertical conv

    const int b   = blockIdx.z;
    const int x0  = blockIdx.x * TX;
    const int y0  = blockIdx.y * TY;
    const int tid = threadIdx.x;

    const float* in = cin + (long)b * PLANE;

    const bool interior = (x0 >= PADX) && (x0 - PADX + LW <= IMG_W)
                       && (y0 >= HALO) && (y0 + TY + HALO <= IMG_H);

    // ---------------- load tile ----------------
    if (interior) {
        constexpr int RSTRIDE = 256 / LW4;          // 13, 13, 12
        constexpr int WORKERS = RSTRIDE * LW4;      // 247, 247, 240
        if (tid < WORKERS) {
            const int c4 = tid % LW4;
            const int rs = tid / LW4;
            const float4* inr = (const float4*)(in + (long)(y0 - HALO) * IMG_W
                                                   + (x0 - PADX));
            #pragma unroll
            for (int r = rs; r < SH; r += RSTRIDE)
                *(float4*)&s0[r][c4 * 4] = inr[(long)r * W4 + c4];
        }
    } else {
        for (int i = tid; i < SH * LW; i += 256) {
            int r = i / LW, c = i - r * LW;
            int gy = y0 + r - HALO;
            int gx = x0 + c - PADX;
            gy = gy < 0 ? -gy : (gy >= IMG_H ? 2 * IMG_H - 2 - gy : gy);
            gx = gx < 0 ? -gx : (gx >= IMG_W ? 2 * IMG_W - 2 - gx : gx);
            s0[r][c] = in[gy * IMG_W + gx];
        }
    }
    __syncthreads();

    // ------- vertical 5-tap (dilation D): chains of 4 rows spaced D apart -------
    // Output rows r0+i*D (i=0..3) share tap rows s0[r0+m*D], m=0..7.
    {
        constexpr int NW = 8 * LW4;                 // 152, 152, 160 workers
        if (tid < NW) {
            const int c4 = tid % LW4;
            const int h  = tid / LW4;               // chain id 0..7
            const int p  = h & (D - 1);             // phase (D is pow2)
            const int k  = h / D;
            const int r0 = p + 4 * k * D;
            float4 t[8];
            #pragma unroll
            for (int m = 0; m < 8; m++)
                t[m] = *(const float4*)&s0[r0 + m * D][c4 * 4];
            #pragma unroll
            for (int i = 0; i < 4; i++) {
                float4 v;
                v.x = 0.0625f * (t[i].x + t[i+4].x) + 0.25f * (t[i+1].x + t[i+3].x) + 0.375f * t[i+2].x;
                v.y = 0.0625f * (t[i].y + t[i+4].y) + 0.25f * (t[i+1].y + t[i+3].y) + 0.375f * t[i+2].y;
                v.z = 0.0625f * (t[i].z + t[i+4].z) + 0.25f * (t[i+1].z + t[i+3].z) + 0.375f * t[i+2].z;
                v.w = 0.0625f * (t[i].w + t[i+4].w) + 0.25f * (t[i+1].w + t[i+3].w) + 0.375f * t[i+2].w;
                *(float4*)&s1[r0 + i * D][c4 * 4] = v;
            }
        }
    }
    __syncthreads();

    // ------- horizontal 5-tap + write w and c_next -------
    // Thread -> row r = tid>>3, column pair {pc, pc+8}: conflict-free LDS rows,
    // fully coalesced 128B STG rows.
    {
        const int r  = tid >> 3;     // 0..31
        const int pc = tid & 7;      // 0..7
        float* wo = wout + (long)b * wbs;
        float* co = cout + (long)b * cbs;

        #pragma unroll
        for (int s = 0; s < 2; s++) {
            const int oc = pc + s * 8;               // output float4 col 0..15
            float4 v;
            if constexpr (D == 4) {
                const float* row = s1[r];
                float4 A0 = *(const float4*)&row[(oc + 0) * 4];
                float4 A1 = *(const float4*)&row[(oc + 1) * 4];
                float4 A2 = *(const float4*)&row[(oc + 2) * 4];
                float4 A3 = *(const float4*)&row[(oc + 3) * 4];
                float4 A4 = *(const float4*)&row[(oc + 4) * 4];
                v.x = 0.0625f * (A0.x + A4.x) + 0.25f * (A1.x + A3.x) + 0.375f * A2.x;
                v.y = 0.0625f * (A0.y + A4.y) + 0.25f * (A1.y + A3.y) + 0.375f * A2.y;
                v.z = 0.0625f * (A0.z + A4.z) + 0.25f * (A1.z + A3.z) + 0.375f * A2.z;
                v.w = 0.0625f * (A0.w + A4.w) + 0.25f * (A1.w + A3.w) + 0.375f * A2.w;
            } else {
                const float* row = s1[r];
                float4 B0 = *(const float4*)&row[(oc + 0) * 4];
                float4 B1 = *(const float4*)&row[(oc + 1) * 4];
                float4 B2 = *(const float4*)&row[(oc + 2) * 4];
                float f[12] = {B0.x, B0.y, B0.z, B0.w,
                               B1.x, B1.y, B1.z, B1.w,
                               B2.x, B2.y, B2.z, B2.w};
                v.x = 0.0625f * (f[4 - 2*D] + f[4 + 2*D]) + 0.25f * (f[4 - D] + f[4 + D]) + 0.375f * f[4];
                v.y = 0.0625f * (f[5 - 2*D] + f[5 + 2*D]) + 0.25f * (f[5 - D] + f[5 + D]) + 0.375f * f[5];
                v.z = 0.0625f * (f[6 - 2*D] + f[6 + 2*D]) + 0.25f * (f[6 - D] + f[6 + D]) + 0.375f * f[6];
                v.w = 0.0625f * (f[7 - 2*D] + f[7 + 2*D]) + 0.25f * (f[7 - D] + f[7 + D]) + 0.375f * f[7];
            }
            float4 cc = *(const float4*)&s0[r + HALO][(oc + PAD4) * 4];
            float4 w4 = make_float4(cc.x - v.x, cc.y - v.y, cc.z - v.z, cc.w - v.w);
            const long o = (long)(y0 + r) * W4 + (x0 >> 2) + oc;
            ((float4*)wo)[o] = w4;
            ((float4*)co)[o] = v;
        }
    }
}

extern "C" void kernel_launch(void* const* d_in, const int* in_sizes, int n_in,
                              void* d_out, int out_size)
{
    (void)in_sizes; (void)n_in; (void)out_size;
    const float* x = (const float*)d_in[0];
    float* out = (float*)d_out;

    float *c1, *c2;
    cudaGetSymbolAddress((void**)&c1, g_scratch1);
    cudaGetSymbolAddress((void**)&c2, g_scratch2);

    dim3 block(256, 1, 1);
    dim3 grid(IMG_W / 64, IMG_H / 32, NBATCH);

    const long IN_BS  = (long)PLANE;
    const long OUT_BS = 4L * PLANE;

    uwt_level_kernel<1><<<grid, block>>>(x,  out + 0L * PLANE, OUT_BS, c1, IN_BS);
    uwt_level_kernel<2><<<grid, block>>>(c1, out + 1L * PLANE, OUT_BS, c2, IN_BS);
    uwt_level_kernel<4><<<grid, block>>>(c2, out + 2L * PLANE, OUT_BS,
                                             out + 3L * PLANE, OUT_BS);
}